// round 8
// baseline (speedup 1.0000x reference)
#include <cuda_runtime.h>
#include <cstdint>

// RoPE for Wan S2V: x (1, S, N, D) fp32 with S = f*h*w, N=16, D=128 (C = 64).
// Channel c's angle source:
//   c <  22        -> freqs[f_idx][c]
//   22 <= c < 43   -> freqs[h_idx][c]
//   43 <= c < 64   -> freqs[w_idx][c]
// out pairs: (xr*cos - xi*sin, xr*sin + xi*cos), interleaved in last dim.
//
// R8 (= R6/R7 re-submitted after broker timeouts): 8 positions per block
// (grid = S/8 = 4095), depth-4 software pipeline. All 512 threads stage the
// 8 positions' tables (8*64 = 512, exact fit) as interleaved (cos,sin) float2
// -> per-position table read is one conflict-free LDS.128. One barrier per 8
// positions. 4 LDG.128 kept in flight continuously: iteration p consumes slot
// p&3 and immediately re-issues load p+4 into it. Streaming hints
// (__ldcs/__stcs) — x/out have zero reuse.

#define F_DIM 22
#define H_DIM 21
#define C_DIM 64                       // F_DIM + H_DIM + W_DIM
#define N_HEADS 16
#define D_DIM 128
#define VEC_PER_POS (N_HEADS * D_DIM / 4)   // 512 float4 per position
#define PPB 8                          // positions per block
#define PIPE 4                         // loads in flight

__global__ __launch_bounds__(VEC_PER_POS)
void rope3d_kernel(const float4* __restrict__ x,
                   const float*  __restrict__ fcos,
                   const float*  __restrict__ fsin,
                   const int*    __restrict__ p_h,
                   const int*    __restrict__ p_w,
                   float4*       __restrict__ out,
                   int s_total)
{
    __shared__ float2 tab[PPB * C_DIM];   // (cos, sin) interleaved per channel

    const int t    = threadIdx.x;
    const int base = blockIdx.x * PPB;
    const bool full = (base + PPB) <= s_total;   // uniform per block

    const size_t idx0 = (size_t)base * VEC_PER_POS + t;
    const int c0 = (t & 31) * 2;          // channel pair for this thread

    float4 v[PIPE];

    if (full) {
        // ── Prologue: 4 outstanding DRAM requests per thread.
#pragma unroll
        for (int p = 0; p < PIPE; p++)
            v[p] = __ldcs(x + idx0 + (size_t)p * VEC_PER_POS);

        // ── Stage all 8 positions' tables (512 threads, exact fit).
        {
            const int p = t >> 6;
            const int c = t & 63;
            const int s = base + p;
            const int hh = *p_h;
            const int ww = *p_w;
            const int hw = hh * ww;
            const int fi  = s / hw;
            const int rem = s - fi * hw;
            const int hi  = rem / ww;
            const int wi  = rem - hi * ww;
            const int row = (c < F_DIM) ? fi : ((c < F_DIM + H_DIM) ? hi : wi);
            const int off = row * C_DIM + c;
            tab[t] = make_float2(fcos[off], fsin[off]);
        }
        __syncthreads();

        // ── Pipelined mainloop: consume slot p&3, re-issue load p+4 into it.
#pragma unroll
        for (int p = 0; p < PPB; p++) {
            const float4 cur = v[p & (PIPE - 1)];
            if (p + PIPE < PPB)
                v[p & (PIPE - 1)] =
                    __ldcs(x + idx0 + (size_t)(p + PIPE) * VEC_PER_POS);

            const float4 tv =
                *reinterpret_cast<const float4*>(&tab[p * C_DIM + c0]);
            // tv = (cos_c0, sin_c0, cos_c0+1, sin_c0+1)
            float4 r;
            r.x = cur.x * tv.x - cur.y * tv.y;
            r.y = cur.x * tv.y + cur.y * tv.x;
            r.z = cur.z * tv.z - cur.w * tv.w;
            r.w = cur.z * tv.w + cur.w * tv.z;
            __stcs(out + idx0 + (size_t)p * VEC_PER_POS, r);
        }
    } else {
        // ── Tail block (never taken for S % 8 == 0, kept for safety).
        if (t < PPB * C_DIM) {
            const int p = t >> 6;
            const int c = t & 63;
            const int s = base + p;
            if (s < s_total) {
                const int hh = *p_h;
                const int ww = *p_w;
                const int hw = hh * ww;
                const int fi  = s / hw;
                const int rem = s - fi * hw;
                const int hi  = rem / ww;
                const int wi  = rem - hi * ww;
                const int row = (c < F_DIM) ? fi
                              : ((c < F_DIM + H_DIM) ? hi : wi);
                const int off = row * C_DIM + c;
                tab[t] = make_float2(fcos[off], fsin[off]);
            }
        }
        __syncthreads();

        for (int p = 0; p < PPB; p++) {
            if (base + p >= s_total) break;
            const float4 cur = __ldcs(x + idx0 + (size_t)p * VEC_PER_POS);
            const float4 tv =
                *reinterpret_cast<const float4*>(&tab[p * C_DIM + c0]);
            float4 r;
            r.x = cur.x * tv.x - cur.y * tv.y;
            r.y = cur.x * tv.y + cur.y * tv.x;
            r.z = cur.z * tv.z - cur.w * tv.w;
            r.w = cur.z * tv.w + cur.w * tv.z;
            __stcs(out + idx0 + (size_t)p * VEC_PER_POS, r);
        }
    }
}

extern "C" void kernel_launch(void* const* d_in, const int* in_sizes, int n_in,
                              void* d_out, int out_size)
{
    const float4* x    = (const float4*)d_in[0];
    const float*  fcos = (const float*)d_in[1];
    const float*  fsin = (const float*)d_in[2];
    const int*    ph   = (const int*)d_in[4];
    const int*    pw   = (const int*)d_in[5];
    float4*       out  = (float4*)d_out;

    int s_total = in_sizes[0] / (N_HEADS * D_DIM);   // 32760
    if (s_total <= 0) s_total = out_size / (N_HEADS * D_DIM);

    const int grid = (s_total + PPB - 1) / PPB;
    rope3d_kernel<<<grid, VEC_PER_POS>>>(x, fcos, fsin, ph, pw, out, s_total);
}

// round 10
// speedup vs baseline: 1.0187x; 1.0187x over previous
#include <cuda_runtime.h>
#include <cstdint>

// RoPE for Wan S2V: x (1, S, N, D) fp32 with S = f*h*w, N=16, D=128 (C = 64).
// Channel c's angle source:
//   c <  22        -> freqs[f_idx][c]
//   22 <= c < 43   -> freqs[h_idx][c]
//   43 <= c < 64   -> freqs[w_idx][c]
// out pairs: (xr*cos - xi*sin, xr*sin + xi*cos), interleaved in last dim.
//
// R10 (= R9 resubmitted after broker timeout): PPB=8, ALL 8 LDG.128
// front-batched before the barrier (MLP_p1 = 8, no pipeline). Deliberately
// trades occupancy (~8 payload float4 in regs) for 2x the in-flight DRAM
// requests per thread vs R5/R8, to discriminate "throughput ceiling" vs
// "residual latency exposure". Tables staged as interleaved (cos,sin)
// float2 -> one conflict-free LDS.128 per position. One barrier per 8
// positions. __ldcs/__stcs since x/out have zero reuse.

#define F_DIM 22
#define H_DIM 21
#define C_DIM 64                       // F_DIM + H_DIM + W_DIM
#define N_HEADS 16
#define D_DIM 128
#define VEC_PER_POS (N_HEADS * D_DIM / 4)   // 512 float4 per position
#define PPB 8                          // positions per block

__global__ __launch_bounds__(VEC_PER_POS)
void rope3d_kernel(const float4* __restrict__ x,
                   const float*  __restrict__ fcos,
                   const float*  __restrict__ fsin,
                   const int*    __restrict__ p_h,
                   const int*    __restrict__ p_w,
                   float4*       __restrict__ out,
                   int s_total)
{
    __shared__ float2 tab[PPB * C_DIM];   // (cos, sin) interleaved per channel

    const int t    = threadIdx.x;
    const int base = blockIdx.x * PPB;
    const bool full = (base + PPB) <= s_total;   // uniform per block

    const size_t idx0 = (size_t)base * VEC_PER_POS + t;
    const int c0 = (t & 31) * 2;          // channel pair for this thread

    if (full) {
        // ── Front-batch ALL 8 loads: 8 outstanding DRAM requests/thread.
        float4 v[PPB];
#pragma unroll
        for (int p = 0; p < PPB; p++)
            v[p] = __ldcs(x + idx0 + (size_t)p * VEC_PER_POS);

        // ── Stage all 8 positions' tables (512 threads, exact fit);
        //    overlaps the loads above.
        {
            const int p = t >> 6;
            const int c = t & 63;
            const int s = base + p;
            const int hh = *p_h;
            const int ww = *p_w;
            const int hw = hh * ww;
            const int fi  = s / hw;
            const int rem = s - fi * hw;
            const int hi  = rem / ww;
            const int wi  = rem - hi * ww;
            const int row = (c < F_DIM) ? fi : ((c < F_DIM + H_DIM) ? hi : wi);
            const int off = row * C_DIM + c;
            tab[t] = make_float2(fcos[off], fsin[off]);
        }
        __syncthreads();

        // ── Compute + store all 8.
#pragma unroll
        for (int p = 0; p < PPB; p++) {
            const float4 tv =
                *reinterpret_cast<const float4*>(&tab[p * C_DIM + c0]);
            // tv = (cos_c0, sin_c0, cos_c0+1, sin_c0+1)
            float4 r;
            r.x = v[p].x * tv.x - v[p].y * tv.y;
            r.y = v[p].x * tv.y + v[p].y * tv.x;
            r.z = v[p].z * tv.z - v[p].w * tv.w;
            r.w = v[p].z * tv.w + v[p].w * tv.z;
            __stcs(out + idx0 + (size_t)p * VEC_PER_POS, r);
        }
    } else {
        // ── Tail block (never taken for S % 8 == 0, kept for safety).
        if (t < PPB * C_DIM) {
            const int p = t >> 6;
            const int c = t & 63;
            const int s = base + p;
            if (s < s_total) {
                const int hh = *p_h;
                const int ww = *p_w;
                const int hw = hh * ww;
                const int fi  = s / hw;
                const int rem = s - fi * hw;
                const int hi  = rem / ww;
                const int wi  = rem - hi * ww;
                const int row = (c < F_DIM) ? fi
                              : ((c < F_DIM + H_DIM) ? hi : wi);
                const int off = row * C_DIM + c;
                tab[t] = make_float2(fcos[off], fsin[off]);
            }
        }
        __syncthreads();

        for (int p = 0; p < PPB; p++) {
            if (base + p >= s_total) break;
            const float4 cur = __ldcs(x + idx0 + (size_t)p * VEC_PER_POS);
            const float4 tv =
                *reinterpret_cast<const float4*>(&tab[p * C_DIM + c0]);
            float4 r;
            r.x = cur.x * tv.x - cur.y * tv.y;
            r.y = cur.x * tv.y + cur.y * tv.x;
            r.z = cur.z * tv.z - cur.w * tv.w;
            r.w = cur.z * tv.w + cur.w * tv.z;
            __stcs(out + idx0 + (size_t)p * VEC_PER_POS, r);
        }
    }
}

extern "C" void kernel_launch(void* const* d_in, const int* in_sizes, int n_in,
                              void* d_out, int out_size)
{
    const float4* x    = (const float4*)d_in[0];
    const float*  fcos = (const float*)d_in[1];
    const float*  fsin = (const float*)d_in[2];
    const int*    ph   = (const int*)d_in[4];
    const int*    pw   = (const int*)d_in[5];
    float4*       out  = (float4*)d_out;

    int s_total = in_sizes[0] / (N_HEADS * D_DIM);   // 32760
    if (s_total <= 0) s_total = out_size / (N_HEADS * D_DIM);

    const int grid = (s_total + PPB - 1) / PPB;
    rope3d_kernel<<<grid, VEC_PER_POS>>>(x, fcos, fsin, ph, pw, out, s_total);
}